// round 8
// baseline (speedup 1.0000x reference)
#include <cuda_runtime.h>
#include <math.h>

#define H 512
#define W 512
#define HW (H*W)
#define CH 32
#define CHW (CH*HW)
#define OD2 518            // output dim of pad-4 conv
#define S2 (OD2*OD2)
#define TILE 16
#define ICB 4

// ---------------- scratch (static __device__, no allocation) ----------------
__device__ float g_t1[CHW];          // conv e1 raw output
__device__ float g_t1n[CHW];         // relu(bn(t1))
__device__ float g_t2[CHW];          // conv e2 raw output
__device__ float g_t2n[CHW];         // bn(t2)
__device__ float g_gates[4*CHW];     // f,i,c,o raw conv outputs
__device__ float g_r1[CHW];          // conv r1 raw output
__device__ float g_r2[3*S2];         // conv r2 raw output (518x518)
__device__ double g_sum[8*32];       // per-stage per-channel sum
__device__ double g_sq[8*32];        // per-stage per-channel sum of squares
__device__ float g_mean[8*32];
__device__ float g_rs[8*32];

// ---------------- f32x2 packed-math helpers ----------------
__device__ __forceinline__ unsigned long long dup2(float v) {
    unsigned long long d;
    asm("mov.b64 %0, {%1, %1};" : "=l"(d) : "f"(v));
    return d;
}
__device__ __forceinline__ void fma2(unsigned long long& d,
                                     unsigned long long a, unsigned long long b) {
    asm("fma.rn.f32x2 %0, %1, %2, %0;" : "+l"(d) : "l"(a), "l"(b));
}
__device__ __forceinline__ float2 unpack2(unsigned long long d) {
    float2 f;
    asm("mov.b64 {%0, %1}, %2;" : "=f"(f.x), "=f"(f.y) : "l"(d));
    return f;
}

// ---------------- cp.async helpers ----------------
__device__ __forceinline__ void cp4(unsigned int dst, const float* src, bool pred) {
    int sz = pred ? 4 : 0;
    asm volatile("cp.async.ca.shared.global [%0], [%1], 4, %2;\n"
                 :: "r"(dst), "l"(src), "r"(sz));
}
__device__ __forceinline__ void cp_commit() {
    asm volatile("cp.async.commit_group;");
}
template<int N> __device__ __forceinline__ void cp_wait() {
    asm volatile("cp.async.wait_group %0;" :: "n"(N));
}

// ---------------- small kernels ----------------
__global__ void zero_stats() {
    int i = threadIdx.x;
    g_sum[i] = 0.0; g_sq[i] = 0.0;
}

__global__ void finalize_stats(int stage_base, int nch, double invN) {
    int stage = stage_base + blockIdx.x;
    int t = threadIdx.x;
    if (t < nch) {
        int idx = stage*32 + t;
        double m  = g_sum[idx]*invN;
        double var = g_sq[idx]*invN - m*m;
        g_mean[idx] = (float)m;
        g_rs[idx]   = (float)(1.0 / sqrt(var + 1e-5));
    }
}

// normalize passes (float4): RELU -> relu(bn(x)), else bn(x)
template<int RELU>
__global__ void __launch_bounds__(256)
normalize(const float* __restrict__ in, float* __restrict__ out, int stage)
{
    long i4 = (long)blockIdx.x * 256 + threadIdx.x;      // float4 index
    if (i4 >= CHW/4) return;
    int c = (int)(i4 / (HW/4));
    float m = g_mean[stage*32 + c], rs = g_rs[stage*32 + c];
    float4 v = ((const float4*)in)[i4];
    v.x = (v.x - m)*rs; v.y = (v.y - m)*rs; v.z = (v.z - m)*rs; v.w = (v.w - m)*rs;
    if (RELU) {
        v.x = v.x > 0.f ? v.x : 0.f; v.y = v.y > 0.f ? v.y : 0.f;
        v.z = v.z > 0.f ? v.z : 0.f; v.w = v.w > 0.f ? v.w : 0.f;
    }
    ((float4*)out)[i4] = v;
}

// ---------------- FFMA2 conv3x3, per-warp barrier-free pipeline --------------
// CTA = 8 warps; each warp owns a 32x4 output tile with a private
// double-buffered cp.async halo (ICB x 6 x 36). No __syncthreads in mainloop.
// Weights for ALL chunks preloaded once (one barrier at start).
// Thread = 4 px (tx = lane&7) x 16 oc (8 oc-pairs), row = lane>>3.
// blockIdx.z = gate*2 + oc_half.
// SPLIT=1: channel c<32 from in2 (prev_h), c>=32 from in (t2n).
template<int CIN, int SPLIT>
__global__ void __launch_bounds__(256, 2)
conv2w(const float* __restrict__ in, const float* __restrict__ in2,
       const float* __restrict__ w0_, const float* __restrict__ w1_,
       const float* __restrict__ w2_, const float* __restrict__ w3_,
       float* __restrict__ out, long outStrideZ,
       double* __restrict__ o_sum, double* __restrict__ o_sq)
{
    constexpr int NCH  = CIN / ICB;
    constexpr int BUFE = ICB*6*36;            // 864 floats per buffer

    extern __shared__ float dyn[];
    float* s_w    = dyn;                       // [CIN][9][16]
    float* s_bufs = dyn + CIN*144;             // [8 warps][2][864]
    float* s_red  = s_bufs + 8*2*BUFE;         // [8][16][2]

    const int z    = blockIdx.z;
    const int gate = z >> 1;
    const int ocbase = (z & 1) * 16;
    const float* wt = (gate == 0) ? w0_ : (gate == 1) ? w1_ : (gate == 2) ? w2_ : w3_;
    out   += (long)gate * outStrideZ;
    o_sum += gate*32 + ocbase;
    o_sq  += gate*32 + ocbase;

    const int tid  = threadIdx.x;
    const int wid  = tid >> 5, lane = tid & 31;
    const int tx   = lane & 7, tyw = lane >> 3;
    const int x0   = blockIdx.x*32;
    const int y0   = blockIdx.y*32 + wid*4;
    const int gx0  = x0 - 1;
    const int gy0  = y0 - 1;
    float* mybuf = s_bufs + wid*2*BUFE;

    unsigned long long acc[4][8];
#pragma unroll
    for (int p = 0; p < 4; p++)
#pragma unroll
        for (int q = 0; q < 8; q++) acc[p][q] = 0ULL;

    // per-warp issue of input chunk `ch` into buffer `b`
    auto issue = [&](int ch, int b) {
        const int ic0 = ch * ICB;
        float* dst0 = mybuf + b*BUFE;
#pragma unroll
        for (int j = 0; j < BUFE/32; j++) {       // 27 cp per lane
            int e  = lane + j*32;
            int ic = e / 216;
            int r  = e - ic*216;
            int ly = r / 36, lx = r - ly*36;
            int gy = gy0 + ly, gx = gx0 + lx;
            bool ok = (lx < 34) && ((unsigned)gy < (unsigned)H)
                                && ((unsigned)gx < (unsigned)W);
            int c = ic0 + ic;
            const float* src;
            if (SPLIT && c < 32)
                src = ok ? &in2[(long)c*HW + gy*W + gx] : in2;
            else {
                int cc = SPLIT ? c - 32 : c;
                src = ok ? &in[(long)cc*HW + gy*W + gx] : in;
            }
            cp4((unsigned int)__cvta_generic_to_shared(dst0 + e), src, ok);
        }
        cp_commit();
    };

    // prefetch chunk 0, then load ALL weights (one-time barrier)
    issue(0, 0);
    for (int e = tid; e < CIN*144; e += 256) {
        int ic = e / 144;
        int r  = e - ic*144;
        int k  = r >> 4, oco = r & 15;
        s_w[e] = wt[((long)(ocbase + oco)*CIN + ic)*9 + k];
    }
    __syncthreads();

    for (int n = 0; n < NCH; n++) {
        if (n + 1 < NCH) {
            issue(n + 1, (n + 1) & 1);
            cp_wait<1>();
        } else {
            cp_wait<0>();
        }
        __syncwarp();

        const float* cb = mybuf + (n & 1)*BUFE;
#pragma unroll
        for (int i = 0; i < ICB; i++) {
            const float* wrow = s_w + (n*ICB + i)*144;
#pragma unroll
            for (int r = 0; r < 3; r++) {
                const float* ip = cb + (i*6 + tyw + r)*36 + tx*4;
                float4 va = *(const float4*)ip;
                float2 vb = *(const float2*)(ip + 4);
                unsigned long long d[6] = { dup2(va.x), dup2(va.y), dup2(va.z),
                                            dup2(va.w), dup2(vb.x), dup2(vb.y) };
#pragma unroll
                for (int c = 0; c < 3; c++) {
                    const ulonglong2* wr = (const ulonglong2*)(wrow + (r*3 + c)*16);
                    ulonglong2 wa = wr[0], wb2 = wr[1], wc = wr[2], wd = wr[3];
                    unsigned long long wv[8] = { wa.x, wa.y, wb2.x, wb2.y,
                                                 wc.x, wc.y, wd.x, wd.y };
#pragma unroll
                    for (int p = 0; p < 4; p++) {
#pragma unroll
                        for (int q = 0; q < 8; q++)
                            fma2(acc[p][q], d[c + p], wv[q]);
                    }
                }
            }
        }
        __syncwarp();
    }

    // ---- output (float4 stores) + BN stats ----
    const long obase = (long)(y0 + tyw)*W + x0 + tx*4;
#pragma unroll
    for (int q = 0; q < 8; q++) {
        float2 v0 = unpack2(acc[0][q]), v1 = unpack2(acc[1][q]);
        float2 v2 = unpack2(acc[2][q]), v3 = unpack2(acc[3][q]);
        float4 lo = make_float4(v0.x, v1.x, v2.x, v3.x);
        float4 hi = make_float4(v0.y, v1.y, v2.y, v3.y);
        *(float4*)(out + (long)(ocbase + 2*q    )*HW + obase) = lo;
        *(float4*)(out + (long)(ocbase + 2*q + 1)*HW + obase) = hi;

        float sl = lo.x + lo.y + lo.z + lo.w;
        float ql = lo.x*lo.x + lo.y*lo.y + lo.z*lo.z + lo.w*lo.w;
        float sh = hi.x + hi.y + hi.z + hi.w;
        float qh = hi.x*hi.x + hi.y*hi.y + hi.z*hi.z + hi.w*hi.w;
#pragma unroll
        for (int o2 = 16; o2 > 0; o2 >>= 1) {
            sl += __shfl_xor_sync(0xffffffffu, sl, o2);
            ql += __shfl_xor_sync(0xffffffffu, ql, o2);
            sh += __shfl_xor_sync(0xffffffffu, sh, o2);
            qh += __shfl_xor_sync(0xffffffffu, qh, o2);
        }
        if (lane == 0) {
            s_red[(wid*16 + 2*q    )*2 + 0] = sl;
            s_red[(wid*16 + 2*q    )*2 + 1] = ql;
            s_red[(wid*16 + 2*q + 1)*2 + 0] = sh;
            s_red[(wid*16 + 2*q + 1)*2 + 1] = qh;
        }
    }
    __syncthreads();
    if (tid < 16) {
        double s = 0.0, qq = 0.0;
#pragma unroll
        for (int wdx = 0; wdx < 8; wdx++) {
            s  += (double)s_red[(wdx*16 + tid)*2 + 0];
            qq += (double)s_red[(wdx*16 + tid)*2 + 1];
        }
        atomicAdd(&o_sum[tid], s);
        atomicAdd(&o_sq[tid], qq);
    }
}

// ---------------- legacy conv (e1 (CIN=4) and r2 (COUT=3, 518-wide)) ----------
template<int CIN, int COUT, int PAD, int MODE>
__global__ void __launch_bounds__(256)
conv_bn(const float* __restrict__ in, const float* __restrict__ in2,
        const float* __restrict__ w0_, const float* __restrict__ w1_,
        const float* __restrict__ w2_, const float* __restrict__ w3_,
        float* __restrict__ out, long outStrideZ,
        const float* __restrict__ bn_mean, const float* __restrict__ bn_rs,
        double* __restrict__ o_sum, double* __restrict__ o_sq)
{
    constexpr int OWID = W + 2*PAD - 2;
    constexpr int OHEI = H + 2*PAD - 2;

    const int z = blockIdx.z;
    const float* wt = (z == 0) ? w0_ : (z == 1) ? w1_ : (z == 2) ? w2_ : w3_;
    out   += (long)z * outStrideZ;
    o_sum += z * COUT;
    o_sq  += z * COUT;

    __shared__ float s_in[ICB][18][18];
    __shared__ float s_w[ICB][COUT][12];
    __shared__ float s_red[8][COUT][2];

    const int tid = threadIdx.x;
    const int px = tid & 15, py = tid >> 4;
    const int ox = blockIdx.x*TILE + px;
    const int oy = blockIdx.y*TILE + py;
    const bool valid = (ox < OWID) && (oy < OHEI);

    float acc[COUT];
#pragma unroll
    for (int i = 0; i < COUT; i++) acc[i] = 0.f;

    const int gx0 = blockIdx.x*TILE - PAD;
    const int gy0 = blockIdx.y*TILE - PAD;

    for (int ic0 = 0; ic0 < CIN; ic0 += ICB) {
        __syncthreads();
        for (int e = tid; e < ICB*18*18; e += 256) {
            int ic = e / 324; int r = e - ic*324;
            int ly = r / 18, lx = r - ly*18;
            int gy = gy0 + ly, gx = gx0 + lx;
            float v = 0.f;
            if ((unsigned)gy < (unsigned)H && (unsigned)gx < (unsigned)W) {
                int c = ic0 + ic;
                if (MODE == 0) {
                    v = in[(long)c*HW + gy*W + gx];
                } else if (MODE == 1) {
                    float t = in[(long)c*HW + gy*W + gx];
                    t = (t - bn_mean[c]) * bn_rs[c];
                    v = t > 0.f ? t : 0.f;
                } else {
                    if (c < 32) {
                        v = in2[(long)c*HW + gy*W + gx];
                    } else {
                        float t = in[(long)(c-32)*HW + gy*W + gx];
                        v = (t - bn_mean[c-32]) * bn_rs[c-32];
                    }
                }
            }
            s_in[ic][ly][lx] = v;
        }
        for (int e = tid; e < ICB*COUT*12; e += 256) {
            int ic = e / (COUT*12); int r = e - ic*(COUT*12);
            int oc = r / 12, k = r - oc*12;
            s_w[ic][oc][k] = (k < 9) ? wt[((long)oc*CIN + ic0 + ic)*9 + k] : 0.f;
        }
        __syncthreads();

#pragma unroll
        for (int i = 0; i < ICB; i++) {
            float i00 = s_in[i][py+0][px+0], i01 = s_in[i][py+0][px+1], i02 = s_in[i][py+0][px+2];
            float i10 = s_in[i][py+1][px+0], i11 = s_in[i][py+1][px+1], i12 = s_in[i][py+1][px+2];
            float i20 = s_in[i][py+2][px+0], i21 = s_in[i][py+2][px+1], i22 = s_in[i][py+2][px+2];
#pragma unroll
            for (int oc = 0; oc < COUT; oc++) {
                const float4* wp = (const float4*)&s_w[i][oc][0];
                float4 a = wp[0], b = wp[1], c4 = wp[2];
                acc[oc] += i00*a.x + i01*a.y + i02*a.z
                         + i10*a.w + i11*b.x + i12*b.y
                         + i20*b.z + i21*b.w + i22*c4.x;
            }
        }
    }

    const int lane = tid & 31, wid = tid >> 5;
#pragma unroll
    for (int oc = 0; oc < COUT; oc++) {
        float v = valid ? acc[oc] : 0.f;
        if (valid) out[(long)oc*OHEI*OWID + (long)oy*OWID + ox] = v;
        float s = v, q = v*v;
#pragma unroll
        for (int o2 = 16; o2 > 0; o2 >>= 1) {
            s += __shfl_xor_sync(0xffffffffu, s, o2);
            q += __shfl_xor_sync(0xffffffffu, q, o2);
        }
        if (lane == 0) { s_red[wid][oc][0] = s; s_red[wid][oc][1] = q; }
    }
    __syncthreads();
    if (tid < COUT) {
        double s = 0.0, q = 0.0;
#pragma unroll
        for (int wdx = 0; wdx < 8; wdx++) { s += (double)s_red[wdx][tid][0]; q += (double)s_red[wdx][tid][1]; }
        atomicAdd(&o_sum[tid], s);
        atomicAdd(&o_sq[tid], q);
    }
}

// ---------------- LSTM elementwise ----------------
__device__ __forceinline__ float sigmoidf(float x) { return 1.f / (1.f + expf(-x)); }

__global__ void lstm_elem(const float* __restrict__ prev_c, float* __restrict__ out)
{
    long i = (long)blockIdx.x * blockDim.x + threadIdx.x;
    if (i >= CHW) return;
    int c = (int)(i / HW);
    float f  = sigmoidf((g_gates[i]          - g_mean[64  + c]) * g_rs[64  + c]);
    float it = sigmoidf((g_gates[CHW + i]    - g_mean[96  + c]) * g_rs[96  + c]);
    float ct = tanhf(   (g_gates[2L*CHW + i] - g_mean[128 + c]) * g_rs[128 + c]);
    float ot = sigmoidf((g_gates[3L*CHW + i] - g_mean[160 + c]) * g_rs[160 + c]);
    float nc = prev_c[i] * f + it * ct;
    float nh = tanhf(nc) * ot;
    out[i] = nc;
    out[CHW + i] = nh;
}

// ---------------- gather (K=1 -> single pixel at (hx+3, hy+3)) ----------------
__global__ void gather_k(const int* __restrict__ coords,
                         const float* __restrict__ w_oil, const float* __restrict__ b_oil,
                         const float* __restrict__ w_wat, const float* __restrict__ b_wat,
                         const float* __restrict__ w_gas, const float* __restrict__ b_gas,
                         float* __restrict__ out)
{
    int i = threadIdx.x;
    if (i >= 256) return;
    int hx = coords[2*i], hy = coords[2*i+1];
    int row = hx + 3, col = hy + 3;
    float wv[3] = { w_oil[0], w_wat[0], w_gas[0] };
    float bv[3] = { b_oil[0], b_wat[0], b_gas[0] };
#pragma unroll
    for (int ch = 0; ch < 3; ch++) {
        float v = (g_r2[(long)ch*S2 + (long)row*OD2 + col] - g_mean[224 + ch]) * g_rs[224 + ch];
        out[2L*CHW + (long)i*3 + ch] = v * wv[ch] + bv[ch];
    }
}

// ---------------- launch ----------------
extern "C" void kernel_launch(void* const* d_in, const int* in_sizes, int n_in,
                              void* d_out, int out_size)
{
    const float* x      = (const float*)d_in[0];
    const float* prev_c = (const float*)d_in[1];
    const float* prev_h = (const float*)d_in[2];
    const int*   holes  = (const int*)  d_in[3];
    const float* w_e1   = (const float*)d_in[4];
    const float* w_e2   = (const float*)d_in[5];
    const float* w_f    = (const float*)d_in[6];
    const float* w_i    = (const float*)d_in[7];
    const float* w_c    = (const float*)d_in[8];
    const float* w_o    = (const float*)d_in[9];
    const float* w_r1   = (const float*)d_in[10];
    const float* w_r2   = (const float*)d_in[11];
    const float* w_oil  = (const float*)d_in[12];
    const float* b_oil  = (const float*)d_in[13];
    const float* w_wat  = (const float*)d_in[14];
    const float* b_wat  = (const float*)d_in[15];
    const float* w_gas  = (const float*)d_in[16];
    const float* b_gas  = (const float*)d_in[17];
    float* out = (float*)d_out;

    float *t1, *t1n, *t2, *t2n, *gates, *r1, *r2, *mean, *rs;
    double *sum, *sq;
    cudaGetSymbolAddress((void**)&t1,    g_t1);
    cudaGetSymbolAddress((void**)&t1n,   g_t1n);
    cudaGetSymbolAddress((void**)&t2,    g_t2);
    cudaGetSymbolAddress((void**)&t2n,   g_t2n);
    cudaGetSymbolAddress((void**)&gates, g_gates);
    cudaGetSymbolAddress((void**)&r1,    g_r1);
    cudaGetSymbolAddress((void**)&r2,    g_r2);
    cudaGetSymbolAddress((void**)&sum,   g_sum);
    cudaGetSymbolAddress((void**)&sq,    g_sq);
    cudaGetSymbolAddress((void**)&mean,  g_mean);
    cudaGetSymbolAddress((void**)&rs,    g_rs);

    const double invHW = 1.0 / (double)HW;
    const double invS2 = 1.0 / (double)S2;

    // dynamic smem sizes for the warp-pipelined conv
    const int SM32 = (32*144 + 8*2*864 + 256) * 4;   // 74752 B
    const int SM64 = (64*144 + 8*2*864 + 256) * 4;   // 93184 B
    static bool attr_done = false;
    if (!attr_done) {
        cudaFuncSetAttribute(conv2w<32,0>, cudaFuncAttributeMaxDynamicSharedMemorySize, SM32);
        cudaFuncSetAttribute(conv2w<64,1>, cudaFuncAttributeMaxDynamicSharedMemorySize, SM64);
        attr_done = true;
    }

    dim3 blk(256);
    dim3 g32(32, 32, 1);
    dim3 g33(33, 33, 1);
    dim3 gw2(16, 16, 2);   // conv2w: single conv (2 oc-halves)
    dim3 gw8(16, 16, 8);   // conv2w: 4 gates x 2 oc-halves
    const int NB4 = (CHW/4 + 255) / 256;

    zero_stats<<<1, 256>>>();

    // e1: x (4ch) -> t1, stats stage 0 (legacy kernel)
    conv_bn<4, 32, 1, 0><<<g32, blk>>>(x, nullptr, w_e1, w_e1, w_e1, w_e1,
                                       t1, 0, nullptr, nullptr, sum + 0, sq + 0);
    finalize_stats<<<1, 32>>>(0, 32, invHW);

    // t1n = relu(bn(t1))
    normalize<1><<<NB4, 256>>>(t1, t1n, 0);

    // e2: conv(t1n) -> t2, stats stage 1 (warp-pipelined FFMA2)
    conv2w<32, 0><<<gw2, blk, SM32>>>(t1n, nullptr, w_e2, w_e2, w_e2, w_e2,
                                      t2, 0, sum + 32, sq + 32);
    finalize_stats<<<1, 32>>>(1, 32, invHW);

    // t2n = bn(t2)
    normalize<0><<<NB4, 256>>>(t2, t2n, 1);

    // gates: concat(prev_h, t2n) via split pointers, stats stages 2..5
    conv2w<64, 1><<<gw8, blk, SM64>>>(t2n, prev_h, w_f, w_i, w_c, w_o,
                                      gates, (long)CHW, sum + 64, sq + 64);
    finalize_stats<<<4, 32>>>(2, 32, invHW);

    // LSTM pointwise -> next_c, next_h written directly into d_out
    lstm_elem<<<(CHW + 255) / 256, 256>>>(prev_c, out);

    // r1: conv(next_h raw) -> r1, stats stage 6
    conv2w<32, 0><<<gw2, blk, SM32>>>(out + CHW, nullptr, w_r1, w_r1, w_r1, w_r1,
                                      r1, 0, sum + 192, sq + 192);
    finalize_stats<<<1, 32>>>(6, 32, invHW);

    // r2: relu(bn(r1)) -> r2 (3ch, 518x518, pad 4), stats stage 7 (legacy)
    conv_bn<32, 3, 4, 1><<<g33, blk>>>(r1, nullptr, w_r2, w_r2, w_r2, w_r2,
                                       r2, 0, mean + 192, rs + 192, sum + 224, sq + 224);
    finalize_stats<<<1, 32>>>(7, 3, invS2);

    // gather + tiny matmul (K=1 scalar) -> res
    gather_k<<<1, 256>>>(holes, w_oil, b_oil, w_wat, b_wat, w_gas, b_gas, out);
}

// round 9
// speedup vs baseline: 1.1056x; 1.1056x over previous
#include <cuda_runtime.h>
#include <math.h>

#define H 512
#define W 512
#define HW (H*W)
#define CH 32
#define CHW (CH*HW)
#define OD2 518            // output dim of pad-4 conv
#define S2 (OD2*OD2)
#define ICB 4

// ---------------- scratch (static __device__, no allocation) ----------------
__device__ float g_t1[CHW];          // conv e1 raw output
__device__ float g_t1n[CHW];         // relu(bn(t1))
__device__ float g_t2[CHW];          // conv e2 raw output
__device__ float g_t2n[CHW];         // bn(t2)
__device__ float g_gates[4*CHW];     // f,i,c,o raw conv outputs
__device__ float g_r1[CHW];          // conv r1 raw output
__device__ float g_r2[3*S2];         // conv r2 raw output (518x518)
__device__ double g_sum[8*32];       // per-stage per-channel sum
__device__ double g_sq[8*32];        // per-stage per-channel sum of squares
__device__ float g_mean[8*32];
__device__ float g_rs[8*32];

// ---------------- f32x2 packed-math helpers ----------------
__device__ __forceinline__ unsigned long long dup2(float v) {
    unsigned long long d;
    asm("mov.b64 %0, {%1, %1};" : "=l"(d) : "f"(v));
    return d;
}
__device__ __forceinline__ unsigned long long pk2(float lo, float hi) {
    unsigned long long d;
    asm("mov.b64 %0, {%1, %2};" : "=l"(d) : "f"(lo), "f"(hi));
    return d;
}
__device__ __forceinline__ void fma2(unsigned long long& d,
                                     unsigned long long a, unsigned long long b) {
    asm("fma.rn.f32x2 %0, %1, %2, %0;" : "+l"(d) : "l"(a), "l"(b));
}
__device__ __forceinline__ float2 unpack2(unsigned long long d) {
    float2 f;
    asm("mov.b64 {%0, %1}, %2;" : "=f"(f.x), "=f"(f.y) : "l"(d));
    return f;
}

// ---------------- cp.async helpers ----------------
__device__ __forceinline__ void cp4(unsigned int dst, const float* src, bool pred) {
    int sz = pred ? 4 : 0;
    asm volatile("cp.async.ca.shared.global [%0], [%1], 4, %2;\n"
                 :: "r"(dst), "l"(src), "r"(sz));
}
__device__ __forceinline__ void cp_commit() {
    asm volatile("cp.async.commit_group;");
}
template<int N> __device__ __forceinline__ void cp_wait() {
    asm volatile("cp.async.wait_group %0;" :: "n"(N));
}

// ---------------- small kernels ----------------
__global__ void zero_stats() {
    int i = threadIdx.x;
    g_sum[i] = 0.0; g_sq[i] = 0.0;
}

__global__ void finalize_stats(int stage_base, int nch, double invN) {
    int stage = stage_base + blockIdx.x;
    int t = threadIdx.x;
    if (t < nch) {
        int idx = stage*32 + t;
        double m  = g_sum[idx]*invN;
        double var = g_sq[idx]*invN - m*m;
        g_mean[idx] = (float)m;
        g_rs[idx]   = (float)(1.0 / sqrt(var + 1e-5));
    }
}

// normalize passes (float4): RELU -> relu(bn(x)), else bn(x)
template<int RELU>
__global__ void __launch_bounds__(256)
normalize(const float* __restrict__ in, float* __restrict__ out, int stage)
{
    long i4 = (long)blockIdx.x * 256 + threadIdx.x;      // float4 index
    if (i4 >= CHW/4) return;
    int c = (int)(i4 / (HW/4));
    float m = g_mean[stage*32 + c], rs = g_rs[stage*32 + c];
    float4 v = ((const float4*)in)[i4];
    v.x = (v.x - m)*rs; v.y = (v.y - m)*rs; v.z = (v.z - m)*rs; v.w = (v.w - m)*rs;
    if (RELU) {
        v.x = v.x > 0.f ? v.x : 0.f; v.y = v.y > 0.f ? v.y : 0.f;
        v.z = v.z > 0.f ? v.z : 0.f; v.w = v.w > 0.f ? v.w : 0.f;
    }
    ((float4*)out)[i4] = v;
}

// ---------------- FFMA2 conv3x3, block-coop 3-buffer cp.async pipeline -------
// Tile 64x16; thread = 4 px x 16 oc (8 oc-pairs). blockIdx.z = gate*2 + half.
// One __syncthreads per chunk: wait -> sync -> issue(n+2) -> compute(n).
// SPLIT=1: channel c<32 from in2 (prev_h), c>=32 from in (t2n).
template<int CIN, int SPLIT>
__global__ void __launch_bounds__(256, 2)
conv2(const float* __restrict__ in, const float* __restrict__ in2,
      const float* __restrict__ w0_, const float* __restrict__ w1_,
      const float* __restrict__ w2_, const float* __restrict__ w3_,
      float* __restrict__ out, long outStrideZ,
      double* __restrict__ o_sum, double* __restrict__ o_sq)
{
    constexpr int NCH  = CIN / ICB;
    constexpr int BUFI = ICB*18*68;         // padded input buffer stride (4896)
    constexpr int NIN  = ICB*18*66;         // 4752 cp per chunk
    constexpr int NWT  = ICB*9*16;          // 576
    constexpr int NTOT = NIN + NWT;

    extern __shared__ float dyn[];
    float* s_in  = dyn;                     // [3][BUFI]
    float* s_w   = dyn + 3*BUFI;            // [3][NWT]
    float* s_red = s_w + 3*NWT;             // [8*16*2]

    const int z    = blockIdx.z;
    const int gate = z >> 1;
    const int ocbase = (z & 1) * 16;
    const float* wt = (gate == 0) ? w0_ : (gate == 1) ? w1_ : (gate == 2) ? w2_ : w3_;
    out   += (long)gate * outStrideZ;
    o_sum += gate*32 + ocbase;
    o_sq  += gate*32 + ocbase;

    const int tid = threadIdx.x;
    const int tx = tid & 15, ty = tid >> 4;
    const int x0 = blockIdx.x*64 + tx*4;
    const int oy = blockIdx.y*16 + ty;
    const int gx0 = blockIdx.x*64 - 1;
    const int gy0 = blockIdx.y*16 - 1;

    unsigned long long acc[4][8];
#pragma unroll
    for (int p = 0; p < 4; p++)
#pragma unroll
        for (int q = 0; q < 8; q++) acc[p][q] = 0ULL;

    auto issue = [&](int ch) {
        const int b   = ch % 3;
        const int ic0 = ch * ICB;
        float* din = s_in + b*BUFI;
        float* dwt = s_w + b*NWT;
        for (int e = tid; e < NTOT; e += 256) {
            if (e < NIN) {
                int ic = e / (18*66);
                int r  = e - ic*(18*66);
                int ly = r / 66, lx = r - ly*66;
                int gy = gy0 + ly, gx = gx0 + lx;
                bool ok = (unsigned)gy < (unsigned)H && (unsigned)gx < (unsigned)W;
                int c = ic0 + ic;
                const float* src;
                if (SPLIT && c < 32)
                    src = ok ? &in2[(long)c*HW + gy*W + gx] : in2;
                else {
                    int cc = SPLIT ? c - 32 : c;
                    src = ok ? &in[(long)cc*HW + gy*W + gx] : in;
                }
                cp4((unsigned int)__cvta_generic_to_shared(din + ic*(18*68) + ly*68 + lx),
                    src, ok);
            } else {
                int r  = e - NIN;
                int ic = r / 144;
                int r2 = r - ic*144;
                int k  = r2 >> 4, oco = r2 & 15;
                cp4((unsigned int)__cvta_generic_to_shared(dwt + r),
                    &wt[((long)(ocbase + oco)*CIN + ic0 + ic)*9 + k], true);
            }
        }
        cp_commit();
    };

    issue(0);
    if (NCH > 1) issue(1);

    for (int n = 0; n < NCH; n++) {
        if (n + 1 < NCH) cp_wait<1>(); else cp_wait<0>();
        __syncthreads();                       // publishes chunk n; frees buf (n-1)%3
        if (n + 2 < NCH) issue(n + 2);

        const float* cb   = s_in + (n % 3)*BUFI;
        const float* wcb  = s_w  + (n % 3)*NWT;
#pragma unroll
        for (int i = 0; i < ICB; i++) {
            const float* wrow = wcb + i*144;
#pragma unroll
            for (int r = 0; r < 3; r++) {
                const float* ip = cb + (i*18 + ty + r)*68 + tx*4;
                float4 va = *(const float4*)ip;
                float2 vb = *(const float2*)(ip + 4);
                unsigned long long d[6] = { dup2(va.x), dup2(va.y), dup2(va.z),
                                            dup2(va.w), dup2(vb.x), dup2(vb.y) };
#pragma unroll
                for (int c = 0; c < 3; c++) {
                    const ulonglong2* wr = (const ulonglong2*)(wrow + (r*3 + c)*16);
                    ulonglong2 wa = wr[0], wb2 = wr[1], wc = wr[2], wd = wr[3];
                    unsigned long long wv[8] = { wa.x, wa.y, wb2.x, wb2.y,
                                                 wc.x, wc.y, wd.x, wd.y };
#pragma unroll
                    for (int p = 0; p < 4; p++) {
#pragma unroll
                        for (int q = 0; q < 8; q++)
                            fma2(acc[p][q], d[c + p], wv[q]);
                    }
                }
            }
        }
    }

    // ---- output (float4 stores) + BN stats ----
    const int lane = tid & 31, wid = tid >> 5;
    const long obase = (long)oy*W + x0;
#pragma unroll
    for (int q = 0; q < 8; q++) {
        float2 v0 = unpack2(acc[0][q]), v1 = unpack2(acc[1][q]);
        float2 v2 = unpack2(acc[2][q]), v3 = unpack2(acc[3][q]);
        float4 lo = make_float4(v0.x, v1.x, v2.x, v3.x);
        float4 hi = make_float4(v0.y, v1.y, v2.y, v3.y);
        *(float4*)(out + (long)(ocbase + 2*q    )*HW + obase) = lo;
        *(float4*)(out + (long)(ocbase + 2*q + 1)*HW + obase) = hi;

        float sl = lo.x + lo.y + lo.z + lo.w;
        float ql = lo.x*lo.x + lo.y*lo.y + lo.z*lo.z + lo.w*lo.w;
        float sh = hi.x + hi.y + hi.z + hi.w;
        float qh = hi.x*hi.x + hi.y*hi.y + hi.z*hi.z + hi.w*hi.w;
#pragma unroll
        for (int o2 = 16; o2 > 0; o2 >>= 1) {
            sl += __shfl_xor_sync(0xffffffffu, sl, o2);
            ql += __shfl_xor_sync(0xffffffffu, ql, o2);
            sh += __shfl_xor_sync(0xffffffffu, sh, o2);
            qh += __shfl_xor_sync(0xffffffffu, qh, o2);
        }
        if (lane == 0) {
            s_red[(wid*16 + 2*q    )*2 + 0] = sl;
            s_red[(wid*16 + 2*q    )*2 + 1] = ql;
            s_red[(wid*16 + 2*q + 1)*2 + 0] = sh;
            s_red[(wid*16 + 2*q + 1)*2 + 1] = qh;
        }
    }
    __syncthreads();
    if (tid < 16) {
        double s = 0.0, qq = 0.0;
#pragma unroll
        for (int wdx = 0; wdx < 8; wdx++) {
            s  += (double)s_red[(wdx*16 + tid)*2 + 0];
            qq += (double)s_red[(wdx*16 + tid)*2 + 1];
        }
        atomicAdd(&o_sum[tid], s);
        atomicAdd(&o_sq[tid], qq);
    }
}

// ---------------- pipelined r2 conv: CIN=32, COUT=3, PAD=4, out 518x518 ------
// Tile 64x16; thread = 4 px (as 2 px-pairs) x 3 oc. FFMA2 packs pixel pairs.
__global__ void __launch_bounds__(256, 2)
convr2(const float* __restrict__ in, const float* __restrict__ wt,
       float* __restrict__ outg,
       double* __restrict__ o_sum, double* __restrict__ o_sq)
{
    constexpr int NCH  = 8;
    constexpr int BUFI = ICB*18*68;
    constexpr int NIN  = ICB*18*66;

    extern __shared__ float dyn[];
    float* s_in = dyn;                     // [3][BUFI]
    float* s_wr = dyn + 3*BUFI;            // [32][9][4]
    float* s_red = s_wr + 32*36;           // [8*3*2]

    const int tid = threadIdx.x;
    const int tx = tid & 15, ty = tid >> 4;
    const int x0 = blockIdx.x*64;
    const int oy = blockIdx.y*16 + ty;
    const int gx0 = x0 - 4;
    const int gy0 = blockIdx.y*16 - 4;

    unsigned long long acc[2][3];
#pragma unroll
    for (int p = 0; p < 2; p++)
#pragma unroll
        for (int q = 0; q < 3; q++) acc[p][q] = 0ULL;

    auto issue = [&](int ch) {
        const int b   = ch % 3;
        const int ic0 = ch * ICB;
        float* din = s_in + b*BUFI;
        for (int e = tid; e < NIN; e += 256) {
            int ic = e / (18*66);
            int r  = e - ic*(18*66);
            int ly = r / 66, lx = r - ly*66;
            int gy = gy0 + ly, gx = gx0 + lx;
            bool ok = (unsigned)gy < (unsigned)H && (unsigned)gx < (unsigned)W;
            const float* src = ok ? &in[(long)(ic0 + ic)*HW + gy*W + gx] : in;
            cp4((unsigned int)__cvta_generic_to_shared(din + ic*(18*68) + ly*68 + lx),
                src, ok);
        }
        cp_commit();
    };

    issue(0);
    issue(1);
    // preload ALL weights: s_wr[ic][k][oc], oc padded to 4
    for (int e = tid; e < 32*9*3; e += 256) {
        int ic = e / 27;
        int r  = e - ic*27;
        int k  = r / 3, oc = r - k*3;
        s_wr[ic*36 + k*4 + oc] = wt[((long)oc*32 + ic)*9 + k];
    }

    for (int n = 0; n < NCH; n++) {
        if (n + 1 < NCH) cp_wait<1>(); else cp_wait<0>();
        __syncthreads();
        if (n + 2 < NCH) issue(n + 2);

        const float* cb = s_in + (n % 3)*BUFI;
#pragma unroll
        for (int i = 0; i < ICB; i++) {
            const float* wbase = s_wr + (n*ICB + i)*36;
#pragma unroll
            for (int r = 0; r < 3; r++) {
                const float* ip = cb + (i*18 + ty + r)*68 + tx*4;
                float4 va = *(const float4*)ip;
                float2 vb = *(const float2*)(ip + 4);
                unsigned long long q01 = pk2(va.x, va.y);
                unsigned long long q12 = pk2(va.y, va.z);
                unsigned long long q23 = pk2(va.z, va.w);
                unsigned long long q34 = pk2(va.w, vb.x);
                unsigned long long q45 = pk2(vb.x, vb.y);
                unsigned long long pr[3][2] = { {q01, q23}, {q12, q34}, {q23, q45} };
#pragma unroll
                for (int c = 0; c < 3; c++) {
                    float4 w4 = *(const float4*)(wbase + (r*3 + c)*4);
                    unsigned long long w0 = dup2(w4.x), w1 = dup2(w4.y), w2 = dup2(w4.z);
                    fma2(acc[0][0], pr[c][0], w0); fma2(acc[1][0], pr[c][1], w0);
                    fma2(acc[0][1], pr[c][0], w1); fma2(acc[1][1], pr[c][1], w1);
                    fma2(acc[0][2], pr[c][0], w2); fma2(acc[1][2], pr[c][1], w2);
                }
            }
        }
    }

    // ---- bounds-checked output + BN stats (stage 7) ----
    const int lane = tid & 31, wid = tid >> 5;
#pragma unroll
    for (int oc = 0; oc < 3; oc++) {
        float2 u0 = unpack2(acc[0][oc]), u1 = unpack2(acc[1][oc]);
        float v[4] = { u0.x, u0.y, u1.x, u1.y };
        float s = 0.f, q = 0.f;
#pragma unroll
        for (int j = 0; j < 4; j++) {
            int ox = x0 + tx*4 + j;
            bool ok = (ox < OD2) && (oy < OD2);
            float t = ok ? v[j] : 0.f;
            if (ok) outg[(long)oc*S2 + (long)oy*OD2 + ox] = t;
            s += t; q += t*t;
        }
#pragma unroll
        for (int o2 = 16; o2 > 0; o2 >>= 1) {
            s += __shfl_xor_sync(0xffffffffu, s, o2);
            q += __shfl_xor_sync(0xffffffffu, q, o2);
        }
        if (lane == 0) {
            s_red[(wid*3 + oc)*2 + 0] = s;
            s_red[(wid*3 + oc)*2 + 1] = q;
        }
    }
    __syncthreads();
    if (tid < 3) {
        double s = 0.0, qq = 0.0;
#pragma unroll
        for (int wdx = 0; wdx < 8; wdx++) {
            s  += (double)s_red[(wdx*3 + tid)*2 + 0];
            qq += (double)s_red[(wdx*3 + tid)*2 + 1];
        }
        atomicAdd(&o_sum[tid], s);
        atomicAdd(&o_sq[tid], qq);
    }
}

// ---------------- LSTM elementwise (float4, fast transcendentals) ------------
__device__ __forceinline__ float fsig(float x) {
    return __fdividef(1.f, 1.f + __expf(-x));
}
__device__ __forceinline__ float ftanh(float x) {
    float e = __expf(-2.f*x);
    return __fdividef(1.f - e, 1.f + e);
}

__global__ void lstm_elem(const float* __restrict__ prev_c, float* __restrict__ out)
{
    long i4 = (long)blockIdx.x * 256 + threadIdx.x;
    if (i4 >= CHW/4) return;
    int c = (int)(i4 >> 16);                     // HW/4 = 65536 float4 per channel
    float mf = g_mean[64  + c], rf = g_rs[64  + c];
    float mi = g_mean[96  + c], ri = g_rs[96  + c];
    float mc = g_mean[128 + c], rc = g_rs[128 + c];
    float mo = g_mean[160 + c], ro = g_rs[160 + c];

    float4 gf = ((const float4*)g_gates)[i4];
    float4 gi = ((const float4*)(g_gates + CHW))[i4];
    float4 gc = ((const float4*)(g_gates + 2L*CHW))[i4];
    float4 go = ((const float4*)(g_gates + 3L*CHW))[i4];
    float4 pc = ((const float4*)prev_c)[i4];

    float4 ncv, nhv;
    {
        float f = fsig((gf.x - mf)*rf), it = fsig((gi.x - mi)*ri);
        float ct = ftanh((gc.x - mc)*rc), ot = fsig((go.x - mo)*ro);
        ncv.x = pc.x*f + it*ct; nhv.x = ftanh(ncv.x)*ot;
    }
    {
        float f = fsig((gf.y - mf)*rf), it = fsig((gi.y - mi)*ri);
        float ct = ftanh((gc.y - mc)*rc), ot = fsig((go.y - mo)*ro);
        ncv.y = pc.y*f + it*ct; nhv.y = ftanh(ncv.y)*ot;
    }
    {
        float f = fsig((gf.z - mf)*rf), it = fsig((gi.z - mi)*ri);
        float ct = ftanh((gc.z - mc)*rc), ot = fsig((go.z - mo)*ro);
        ncv.z = pc.z*f + it*ct; nhv.z = ftanh(ncv.z)*ot;
    }
    {
        float f = fsig((gf.w - mf)*rf), it = fsig((gi.w - mi)*ri);
        float ct = ftanh((gc.w - mc)*rc), ot = fsig((go.w - mo)*ro);
        ncv.w = pc.w*f + it*ct; nhv.w = ftanh(ncv.w)*ot;
    }
    ((float4*)out)[i4] = ncv;
    ((float4*)(out + CHW))[i4] = nhv;
}

// ---------------- gather (K=1 -> single pixel at (hx+3, hy+3)) ----------------
__global__ void gather_k(const int* __restrict__ coords,
                         const float* __restrict__ w_oil, const float* __restrict__ b_oil,
                         const float* __restrict__ w_wat, const float* __restrict__ b_wat,
                         const float* __restrict__ w_gas, const float* __restrict__ b_gas,
                         float* __restrict__ out)
{
    int i = threadIdx.x;
    if (i >= 256) return;
    int hx = coords[2*i], hy = coords[2*i+1];
    int row = hx + 3, col = hy + 3;
    float wv[3] = { w_oil[0], w_wat[0], w_gas[0] };
    float bv[3] = { b_oil[0], b_wat[0], b_gas[0] };
#pragma unroll
    for (int ch = 0; ch < 3; ch++) {
        float v = (g_r2[(long)ch*S2 + (long)row*OD2 + col] - g_mean[224 + ch]) * g_rs[224 + ch];
        out[2L*CHW + (long)i*3 + ch] = v * wv[ch] + bv[ch];
    }
}

// ---------------- launch ----------------
extern "C" void kernel_launch(void* const* d_in, const int* in_sizes, int n_in,
                              void* d_out, int out_size)
{
    const float* x      = (const float*)d_in[0];
    const float* prev_c = (const float*)d_in[1];
    const float* prev_h = (const float*)d_in[2];
    const int*   holes  = (const int*)  d_in[3];
    const float* w_e1   = (const float*)d_in[4];
    const float* w_e2   = (const float*)d_in[5];
    const float* w_f    = (const float*)d_in[6];
    const float* w_i    = (const float*)d_in[7];
    const float* w_c    = (const float*)d_in[8];
    const float* w_o    = (const float*)d_in[9];
    const float* w_r1   = (const float*)d_in[10];
    const float* w_r2   = (const float*)d_in[11];
    const float* w_oil  = (const float*)d_in[12];
    const float* b_oil  = (const float*)d_in[13];
    const float* w_wat  = (const float*)d_in[14];
    const float* b_wat  = (const float*)d_in[15];
    const float* w_gas  = (const float*)d_in[16];
    const float* b_gas  = (const float*)d_in[17];
    float* out = (float*)d_out;

    float *t1, *t1n, *t2, *t2n, *gates, *r1, *r2, *mean, *rs;
    double *sum, *sq;
    cudaGetSymbolAddress((void**)&t1,    g_t1);
    cudaGetSymbolAddress((void**)&t1n,   g_t1n);
    cudaGetSymbolAddress((void**)&t2,    g_t2);
    cudaGetSymbolAddress((void**)&t2n,   g_t2n);
    cudaGetSymbolAddress((void**)&gates, g_gates);
    cudaGetSymbolAddress((void**)&r1,    g_r1);
    cudaGetSymbolAddress((void**)&r2,    g_r2);
    cudaGetSymbolAddress((void**)&sum,   g_sum);
    cudaGetSymbolAddress((void**)&sq,    g_sq);
    cudaGetSymbolAddress((void**)&mean,  g_mean);
    cudaGetSymbolAddress((void**)&rs,    g_rs);

    const double invHW = 1.0 / (double)HW;
    const double invS2 = 1.0 / (double)S2;

    // dynamic smem: conv2 = 3 input bufs + 3 weight bufs + reduction
    const int SMC = (3*(ICB*18*68) + 3*(ICB*9*16) + 256) * 4;   // 66688 B
    const int SMR = (3*(ICB*18*68) + 32*36 + 64) * 4;           // 63616 B
    cudaFuncSetAttribute(conv2<32,0>, cudaFuncAttributeMaxDynamicSharedMemorySize, SMC);
    cudaFuncSetAttribute(conv2<64,1>, cudaFuncAttributeMaxDynamicSharedMemorySize, SMC);
    cudaFuncSetAttribute(conv2<4,0>,  cudaFuncAttributeMaxDynamicSharedMemorySize, SMC);
    cudaFuncSetAttribute(convr2,      cudaFuncAttributeMaxDynamicSharedMemorySize, SMR);

    dim3 blk(256);
    dim3 gw2(8, 32, 2);    // conv2: single conv (2 oc-halves)
    dim3 gw8(8, 32, 8);    // conv2: 4 gates x 2 oc-halves
    dim3 gr2(9, 33, 1);    // convr2: 576x528 covers 518x518
    const int NB4 = (CHW/4 + 255) / 256;

    zero_stats<<<1, 256>>>();

    // e1: x (4ch) -> t1, stats stage 0
    conv2<4, 0><<<gw2, blk, SMC>>>(x, nullptr, w_e1, w_e1, w_e1, w_e1,
                                   t1, 0, sum + 0, sq + 0);
    finalize_stats<<<1, 32>>>(0, 32, invHW);

    // t1n = relu(bn(t1))
    normalize<1><<<NB4, 256>>>(t1, t1n, 0);

    // e2: conv(t1n) -> t2, stats stage 1
    conv2<32, 0><<<gw2, blk, SMC>>>(t1n, nullptr, w_e2, w_e2, w_e2, w_e2,
                                    t2, 0, sum + 32, sq + 32);
    finalize_stats<<<1, 32>>>(1, 32, invHW);

    // t2n = bn(t2)
    normalize<0><<<NB4, 256>>>(t2, t2n, 1);

    // gates: concat(prev_h, t2n) via split pointers, stats stages 2..5
    conv2<64, 1><<<gw8, blk, SMC>>>(t2n, prev_h, w_f, w_i, w_c, w_o,
                                    gates, (long)CHW, sum + 64, sq + 64);
    finalize_stats<<<4, 32>>>(2, 32, invHW);

    // LSTM pointwise -> next_c, next_h written directly into d_out
    lstm_elem<<<NB4, 256>>>(prev_c, out);

    // r1: conv(next_h raw) -> r1, stats stage 6
    conv2<32, 0><<<gw2, blk, SMC>>>(out + CHW, nullptr, w_r1, w_r1, w_r1, w_r1,
                                    r1, 0, sum + 192, sq + 192);
    finalize_stats<<<1, 32>>>(6, 32, invHW);

    // normalize r1 -> reuse t1n buffer as relu(bn(r1))
    normalize<1><<<NB4, 256>>>(r1, t1n, 6);

    // r2: conv(relu(bn(r1))) -> r2 (3ch, 518x518, pad 4), stats stage 7
    convr2<<<gr2, blk, SMR>>>(t1n, w_r2, r2, sum + 224, sq + 224);
    finalize_stats<<<1, 32>>>(7, 3, invS2);

    // gather + tiny matmul (K=1 scalar) -> res
    gather_k<<<1, 256>>>(holes, w_oil, b_oil, w_wat, b_wat, w_gas, b_gas, out);
}

// round 10
// speedup vs baseline: 1.1376x; 1.0289x over previous
#include <cuda_runtime.h>
#include <math.h>

#define H 512
#define W 512
#define HW (H*W)
#define CH 32
#define CHW (CH*HW)
#define OD2 518            // output dim of pad-4 conv
#define S2 (OD2*OD2)
#define ICB 4

// ---------------- scratch (static __device__, no allocation) ----------------
__device__ float g_t1[CHW];          // conv e1 raw output
__device__ float g_t1n[CHW];         // relu(bn(t1))
__device__ float g_t2[CHW];          // conv e2 raw output
__device__ float g_t2n[CHW];         // bn(t2)
__device__ float g_gates[4*CHW];     // f,i,c,o raw conv outputs
__device__ float g_r1[CHW];          // conv r1 raw output
__device__ float g_r2[3*S2];         // conv r2 raw output (518x518)
__device__ double g_sum[8*32];       // per-stage per-channel sum
__device__ double g_sq[8*32];        // per-stage per-channel sum of squares
__device__ float g_mean[8*32];
__device__ float g_rs[8*32];

// ---------------- f32x2 packed-math helpers ----------------
__device__ __forceinline__ unsigned long long dup2(float v) {
    unsigned long long d;
    asm("mov.b64 %0, {%1, %1};" : "=l"(d) : "f"(v));
    return d;
}
__device__ __forceinline__ unsigned long long pk2(float lo, float hi) {
    unsigned long long d;
    asm("mov.b64 %0, {%1, %2};" : "=l"(d) : "f"(lo), "f"(hi));
    return d;
}
__device__ __forceinline__ void fma2(unsigned long long& d,
                                     unsigned long long a, unsigned long long b) {
    asm("fma.rn.f32x2 %0, %1, %2, %0;" : "+l"(d) : "l"(a), "l"(b));
}
__device__ __forceinline__ float2 unpack2(unsigned long long d) {
    float2 f;
    asm("mov.b64 {%0, %1}, %2;" : "=f"(f.x), "=f"(f.y) : "l"(d));
    return f;
}

// ---------------- cp.async helpers ----------------
__device__ __forceinline__ void cp4(unsigned int dst, const float* src, bool pred) {
    int sz = pred ? 4 : 0;
    asm volatile("cp.async.ca.shared.global [%0], [%1], 4, %2;\n"
                 :: "r"(dst), "l"(src), "r"(sz));
}
__device__ __forceinline__ void cp_commit() {
    asm volatile("cp.async.commit_group;");
}
template<int N> __device__ __forceinline__ void cp_wait() {
    asm volatile("cp.async.wait_group %0;" :: "n"(N));
}

// ---------------- small kernels ----------------
__global__ void zero_stats() {
    int i = threadIdx.x;
    g_sum[i] = 0.0; g_sq[i] = 0.0;
}

__global__ void finalize_stats(int stage_base, int nch, double invN) {
    int stage = stage_base + blockIdx.x;
    int t = threadIdx.x;
    if (t < nch) {
        int idx = stage*32 + t;
        double m  = g_sum[idx]*invN;
        double var = g_sq[idx]*invN - m*m;
        g_mean[idx] = (float)m;
        g_rs[idx]   = (float)(1.0 / sqrt(var + 1e-5));
    }
}

// normalize passes (float4): RELU -> relu(bn(x)), else bn(x)
template<int RELU>
__global__ void __launch_bounds__(256)
normalize(const float* __restrict__ in, float* __restrict__ out, int stage)
{
    long i4 = (long)blockIdx.x * 256 + threadIdx.x;      // float4 index
    if (i4 >= CHW/4) return;
    int c = (int)(i4 / (HW/4));
    float m = g_mean[stage*32 + c], rs = g_rs[stage*32 + c];
    float4 v = ((const float4*)in)[i4];
    v.x = (v.x - m)*rs; v.y = (v.y - m)*rs; v.z = (v.z - m)*rs; v.w = (v.w - m)*rs;
    if (RELU) {
        v.x = v.x > 0.f ? v.x : 0.f; v.y = v.y > 0.f ? v.y : 0.f;
        v.z = v.z > 0.f ? v.z : 0.f; v.w = v.w > 0.f ? v.w : 0.f;
    }
    ((float4*)out)[i4] = v;
}

// ---------------- FFMA2 conv3x3, cp.async double-buffered (R7 protocol) ------
// Tile: 64 wide x 16 tall; thread = 4 px (x) x 16 oc (8 oc-pairs).
// blockIdx.z = gate*2 + oc_half. Raw inputs only (transform done upstream).
// SPLIT=1: channel c<32 from in2 (prev_h), c>=32 from in (t2n).
template<int CIN, int SPLIT>
__global__ void __launch_bounds__(256, 2)
conv2(const float* __restrict__ in, const float* __restrict__ in2,
      const float* __restrict__ w0_, const float* __restrict__ w1_,
      const float* __restrict__ w2_, const float* __restrict__ w3_,
      float* __restrict__ out, long outStrideZ,
      double* __restrict__ o_sum, double* __restrict__ o_sq)
{
    constexpr int NCH = CIN / ICB;
    constexpr int NIN = ICB*18*66;          // 4752 input elements per chunk
    constexpr int NWT = ICB*9*16;           // 576 weight elements per chunk
    constexpr int NTOT = NIN + NWT;         // 5328

    const int z    = blockIdx.z;
    const int gate = z >> 1;
    const int ocbase = (z & 1) * 16;
    const float* wt = (gate == 0) ? w0_ : (gate == 1) ? w1_ : (gate == 2) ? w2_ : w3_;
    out   += (long)gate * outStrideZ;
    o_sum += gate*32 + ocbase;
    o_sq  += gate*32 + ocbase;

    __shared__ float s_in[2][ICB][18][68];
    __shared__ float s_w[2][ICB][9][16];
    __shared__ float s_red[8][16][2];

    const int tid = threadIdx.x;
    const int tx = tid & 15, ty = tid >> 4;
    const int x0 = blockIdx.x*64 + tx*4;
    const int oy = blockIdx.y*16 + ty;
    const int gx0 = blockIdx.x*64 - 1;
    const int gy0 = blockIdx.y*16 - 1;

    unsigned long long acc[4][8];
#pragma unroll
    for (int p = 0; p < 4; p++)
#pragma unroll
        for (int q = 0; q < 8; q++) acc[p][q] = 0ULL;

    // issue loads for chunk `ch` into buffer `b`
    auto issue = [&](int ch, int b) {
        int ic0 = ch * ICB;
        for (int e = tid; e < NTOT; e += 256) {
            if (e < NIN) {
                int ic = e / (18*66);
                int r  = e - ic*(18*66);
                int ly = r / 66, lx = r - ly*66;
                int gy = gy0 + ly, gx = gx0 + lx;
                bool ok = (unsigned)gy < (unsigned)H && (unsigned)gx < (unsigned)W;
                int c = ic0 + ic;
                const float* src;
                if (SPLIT && c < 32)
                    src = ok ? &in2[(long)c*HW + gy*W + gx] : in2;
                else {
                    int cc = SPLIT ? c - 32 : c;
                    src = ok ? &in[(long)cc*HW + gy*W + gx] : in;
                }
                cp4((unsigned int)__cvta_generic_to_shared(&s_in[b][ic][ly][lx]), src, ok);
            } else {
                int r  = e - NIN;
                int ic = r / 144;
                int r2 = r - ic*144;
                int k  = r2 >> 4, oco = r2 & 15;
                const float* src = &wt[((long)(ocbase + oco)*CIN + ic0 + ic)*9 + k];
                cp4((unsigned int)__cvta_generic_to_shared(&s_w[b][ic][k][oco]), src, true);
            }
        }
        cp_commit();
    };

    issue(0, 0);

    for (int n = 0; n < NCH; n++) {
        const int b = n & 1;
        if (n + 1 < NCH) {
            issue(n + 1, (n + 1) & 1);
            cp_wait<1>();
        } else {
            cp_wait<0>();
        }
        __syncthreads();

#pragma unroll
        for (int i = 0; i < ICB; i++) {
#pragma unroll
            for (int r = 0; r < 3; r++) {
                float4 va = *(const float4*)&s_in[b][i][ty + r][tx*4];
                float2 vb = *(const float2*)&s_in[b][i][ty + r][tx*4 + 4];
                unsigned long long d[6] = { dup2(va.x), dup2(va.y), dup2(va.z),
                                            dup2(va.w), dup2(vb.x), dup2(vb.y) };
#pragma unroll
                for (int c = 0; c < 3; c++) {
                    const ulonglong2* wr = (const ulonglong2*)&s_w[b][i][r*3 + c][0];
                    ulonglong2 wa = wr[0], wb2 = wr[1], wc = wr[2], wd = wr[3];
                    unsigned long long wv[8] = { wa.x, wa.y, wb2.x, wb2.y,
                                                 wc.x, wc.y, wd.x, wd.y };
#pragma unroll
                    for (int p = 0; p < 4; p++) {
#pragma unroll
                        for (int q = 0; q < 8; q++)
                            fma2(acc[p][q], d[c + p], wv[q]);
                    }
                }
            }
        }
        __syncthreads();
    }

    // ---- output (float4 stores) + BN stats ----
    const int lane = tid & 31, wid = tid >> 5;
    const long obase = (long)oy*W + x0;
#pragma unroll
    for (int q = 0; q < 8; q++) {
        float2 v0 = unpack2(acc[0][q]), v1 = unpack2(acc[1][q]);
        float2 v2 = unpack2(acc[2][q]), v3 = unpack2(acc[3][q]);
        float4 lo = make_float4(v0.x, v1.x, v2.x, v3.x);
        float4 hi = make_float4(v0.y, v1.y, v2.y, v3.y);
        *(float4*)(out + (long)(ocbase + 2*q    )*HW + obase) = lo;
        *(float4*)(out + (long)(ocbase + 2*q + 1)*HW + obase) = hi;

        float sl = lo.x + lo.y + lo.z + lo.w;
        float ql = lo.x*lo.x + lo.y*lo.y + lo.z*lo.z + lo.w*lo.w;
        float sh = hi.x + hi.y + hi.z + hi.w;
        float qh = hi.x*hi.x + hi.y*hi.y + hi.z*hi.z + hi.w*hi.w;
#pragma unroll
        for (int o2 = 16; o2 > 0; o2 >>= 1) {
            sl += __shfl_xor_sync(0xffffffffu, sl, o2);
            ql += __shfl_xor_sync(0xffffffffu, ql, o2);
            sh += __shfl_xor_sync(0xffffffffu, sh, o2);
            qh += __shfl_xor_sync(0xffffffffu, qh, o2);
        }
        if (lane == 0) {
            s_red[wid][2*q    ][0] = sl; s_red[wid][2*q    ][1] = ql;
            s_red[wid][2*q + 1][0] = sh; s_red[wid][2*q + 1][1] = qh;
        }
    }
    __syncthreads();
    if (tid < 16) {
        double s = 0.0, qq = 0.0;
#pragma unroll
        for (int wdx = 0; wdx < 8; wdx++) {
            s  += (double)s_red[wdx][tid][0];
            qq += (double)s_red[wdx][tid][1];
        }
        atomicAdd(&o_sum[tid], s);
        atomicAdd(&o_sq[tid], qq);
    }
}

// ---------------- pipelined r2 conv: CIN=32, COUT=3, PAD=4, out 518x518 ------
// Tile 64x16; thread = 4 px (as 2 px-pairs) x 3 oc. FFMA2 packs pixel pairs.
// R7-style double buffer protocol.
__global__ void __launch_bounds__(256, 2)
convr2(const float* __restrict__ in, const float* __restrict__ wt,
       float* __restrict__ outg,
       double* __restrict__ o_sum, double* __restrict__ o_sq)
{
    constexpr int NCH  = 8;
    constexpr int NIN  = ICB*18*66;

    __shared__ float s_in[2][ICB][18][68];
    __shared__ float s_wr[32][9][4];
    __shared__ float s_red[8][3][2];

    const int tid = threadIdx.x;
    const int tx = tid & 15, ty = tid >> 4;
    const int x0 = blockIdx.x*64;
    const int oy = blockIdx.y*16 + ty;
    const int gx0 = x0 - 4;
    const int gy0 = blockIdx.y*16 - 4;

    unsigned long long acc[2][3];
#pragma unroll
    for (int p = 0; p < 2; p++)
#pragma unroll
        for (int q = 0; q < 3; q++) acc[p][q] = 0ULL;

    auto issue = [&](int ch, int b) {
        const int ic0 = ch * ICB;
        for (int e = tid; e < NIN; e += 256) {
            int ic = e / (18*66);
            int r  = e - ic*(18*66);
            int ly = r / 66, lx = r - ly*66;
            int gy = gy0 + ly, gx = gx0 + lx;
            bool ok = (unsigned)gy < (unsigned)H && (unsigned)gx < (unsigned)W;
            const float* src = ok ? &in[(long)(ic0 + ic)*HW + gy*W + gx] : in;
            cp4((unsigned int)__cvta_generic_to_shared(&s_in[b][ic][ly][lx]), src, ok);
        }
        cp_commit();
    };

    issue(0, 0);
    // preload ALL weights: s_wr[ic][k][oc], oc padded to 4
    for (int e = tid; e < 32*9*3; e += 256) {
        int ic = e / 27;
        int r  = e - ic*27;
        int k  = r / 3, oc = r - k*3;
        s_wr[ic][k][oc] = wt[((long)oc*32 + ic)*9 + k];
    }

    for (int n = 0; n < NCH; n++) {
        const int b = n & 1;
        if (n + 1 < NCH) {
            issue(n + 1, (n + 1) & 1);
            cp_wait<1>();
        } else {
            cp_wait<0>();
        }
        __syncthreads();

#pragma unroll
        for (int i = 0; i < ICB; i++) {
            const float* wbase = &s_wr[n*ICB + i][0][0];
#pragma unroll
            for (int r = 0; r < 3; r++) {
                const float* ip = &s_in[b][i][ty + r][tx*4];
                float4 va = *(const float4*)ip;
                float2 vb = *(const float2*)(ip + 4);
                unsigned long long q01 = pk2(va.x, va.y);
                unsigned long long q12 = pk2(va.y, va.z);
                unsigned long long q23 = pk2(va.z, va.w);
                unsigned long long q34 = pk2(va.w, vb.x);
                unsigned long long q45 = pk2(vb.x, vb.y);
                unsigned long long pr[3][2] = { {q01, q23}, {q12, q34}, {q23, q45} };
#pragma unroll
                for (int c = 0; c < 3; c++) {
                    float4 w4 = *(const float4*)(wbase + (r*3 + c)*4);
                    unsigned long long w0 = dup2(w4.x), w1 = dup2(w4.y), w2 = dup2(w4.z);
                    fma2(acc[0][0], pr[c][0], w0); fma2(acc[1][0], pr[c][1], w0);
                    fma2(acc[0][1], pr[c][0], w1); fma2(acc[1][1], pr[c][1], w1);
                    fma2(acc[0][2], pr[c][0], w2); fma2(acc[1][2], pr[c][1], w2);
                }
            }
        }
        __syncthreads();
    }

    // ---- bounds-checked output + BN stats (stage 7) ----
    const int lane = tid & 31, wid = tid >> 5;
#pragma unroll
    for (int oc = 0; oc < 3; oc++) {
        float2 u0 = unpack2(acc[0][oc]), u1 = unpack2(acc[1][oc]);
        float v[4] = { u0.x, u0.y, u1.x, u1.y };
        float s = 0.f, q = 0.f;
#pragma unroll
        for (int j = 0; j < 4; j++) {
            int ox = x0 + tx*4 + j;
            bool ok = (ox < OD2) && (oy < OD2);
            float t = ok ? v[j] : 0.f;
            if (ok) outg[(long)oc*S2 + (long)oy*OD2 + ox] = t;
            s += t; q += t*t;
        }
#pragma unroll
        for (int o2 = 16; o2 > 0; o2 >>= 1) {
            s += __shfl_xor_sync(0xffffffffu, s, o2);
            q += __shfl_xor_sync(0xffffffffu, q, o2);
        }
        if (lane == 0) {
            s_red[wid][oc][0] = s;
            s_red[wid][oc][1] = q;
        }
    }
    __syncthreads();
    if (tid < 3) {
        double s = 0.0, qq = 0.0;
#pragma unroll
        for (int wdx = 0; wdx < 8; wdx++) {
            s  += (double)s_red[wdx][tid][0];
            qq += (double)s_red[wdx][tid][1];
        }
        atomicAdd(&o_sum[tid], s);
        atomicAdd(&o_sq[tid], qq);
    }
}

// ---------------- LSTM elementwise (float4, fast transcendentals) ------------
__device__ __forceinline__ float fsig(float x) {
    return __fdividef(1.f, 1.f + __expf(-x));
}
__device__ __forceinline__ float ftanh(float x) {
    float e = __expf(-2.f*x);
    return __fdividef(1.f - e, 1.f + e);
}

__global__ void lstm_elem(const float* __restrict__ prev_c, float* __restrict__ out)
{
    long i4 = (long)blockIdx.x * 256 + threadIdx.x;
    if (i4 >= CHW/4) return;
    int c = (int)(i4 >> 16);                     // HW/4 = 65536 float4 per channel
    float mf = g_mean[64  + c], rf = g_rs[64  + c];
    float mi = g_mean[96  + c], ri = g_rs[96  + c];
    float mc = g_mean[128 + c], rc = g_rs[128 + c];
    float mo = g_mean[160 + c], ro = g_rs[160 + c];

    float4 gf = ((const float4*)g_gates)[i4];
    float4 gi = ((const float4*)(g_gates + CHW))[i4];
    float4 gc = ((const float4*)(g_gates + 2L*CHW))[i4];
    float4 go = ((const float4*)(g_gates + 3L*CHW))[i4];
    float4 pc = ((const float4*)prev_c)[i4];

    float4 ncv, nhv;
    {
        float f = fsig((gf.x - mf)*rf), it = fsig((gi.x - mi)*ri);
        float ct = ftanh((gc.x - mc)*rc), ot = fsig((go.x - mo)*ro);
        ncv.x = pc.x*f + it*ct; nhv.x = ftanh(ncv.x)*ot;
    }
    {
        float f = fsig((gf.y - mf)*rf), it = fsig((gi.y - mi)*ri);
        float ct = ftanh((gc.y - mc)*rc), ot = fsig((go.y - mo)*ro);
        ncv.y = pc.y*f + it*ct; nhv.y = ftanh(ncv.y)*ot;
    }
    {
        float f = fsig((gf.z - mf)*rf), it = fsig((gi.z - mi)*ri);
        float ct = ftanh((gc.z - mc)*rc), ot = fsig((go.z - mo)*ro);
        ncv.z = pc.z*f + it*ct; nhv.z = ftanh(ncv.z)*ot;
    }
    {
        float f = fsig((gf.w - mf)*rf), it = fsig((gi.w - mi)*ri);
        float ct = ftanh((gc.w - mc)*rc), ot = fsig((go.w - mo)*ro);
        ncv.w = pc.w*f + it*ct; nhv.w = ftanh(ncv.w)*ot;
    }
    ((float4*)out)[i4] = ncv;
    ((float4*)(out + CHW))[i4] = nhv;
}

// ---------------- gather (K=1 -> single pixel at (hx+3, hy+3)) ----------------
__global__ void gather_k(const int* __restrict__ coords,
                         const float* __restrict__ w_oil, const float* __restrict__ b_oil,
                         const float* __restrict__ w_wat, const float* __restrict__ b_wat,
                         const float* __restrict__ w_gas, const float* __restrict__ b_gas,
                         float* __restrict__ out)
{
    int i = threadIdx.x;
    if (i >= 256) return;
    int hx = coords[2*i], hy = coords[2*i+1];
    int row = hx + 3, col = hy + 3;
    float wv[3] = { w_oil[0], w_wat[0], w_gas[0] };
    float bv[3] = { b_oil[0], b_wat[0], b_gas[0] };
#pragma unroll
    for (int ch = 0; ch < 3; ch++) {
        float v = (g_r2[(long)ch*S2 + (long)row*OD2 + col] - g_mean[224 + ch]) * g_rs[224 + ch];
        out[2L*CHW + (long)i*3 + ch] = v * wv[ch] + bv[ch];
    }
}

// ---------------- launch ----------------
extern "C" void kernel_launch(void* const* d_in, const int* in_sizes, int n_in,
                              void* d_out, int out_size)
{
    const float* x      = (const float*)d_in[0];
    const float* prev_c = (const float*)d_in[1];
    const float* prev_h = (const float*)d_in[2];
    const int*   holes  = (const int*)  d_in[3];
    const float* w_e1   = (const float*)d_in[4];
    const float* w_e2   = (const float*)d_in[5];
    const float* w_f    = (const float*)d_in[6];
    const float* w_i    = (const float*)d_in[7];
    const float* w_c    = (const float*)d_in[8];
    const float* w_o    = (const float*)d_in[9];
    const float* w_r1   = (const float*)d_in[10];
    const float* w_r2   = (const float*)d_in[11];
    const float* w_oil  = (const float*)d_in[12];
    const float* b_oil  = (const float*)d_in[13];
    const float* w_wat  = (const float*)d_in[14];
    const float* b_wat  = (const float*)d_in[15];
    const float* w_gas  = (const float*)d_in[16];
    const float* b_gas  = (const float*)d_in[17];
    float* out = (float*)d_out;

    float *t1, *t1n, *t2, *t2n, *gates, *r1, *r2, *mean, *rs;
    double *sum, *sq;
    cudaGetSymbolAddress((void**)&t1,    g_t1);
    cudaGetSymbolAddress((void**)&t1n,   g_t1n);
    cudaGetSymbolAddress((void**)&t2,    g_t2);
    cudaGetSymbolAddress((void**)&t2n,   g_t2n);
    cudaGetSymbolAddress((void**)&gates, g_gates);
    cudaGetSymbolAddress((void**)&r1,    g_r1);
    cudaGetSymbolAddress((void**)&r2,    g_r2);
    cudaGetSymbolAddress((void**)&sum,   g_sum);
    cudaGetSymbolAddress((void**)&sq,    g_sq);
    cudaGetSymbolAddress((void**)&mean,  g_mean);
    cudaGetSymbolAddress((void**)&rs,    g_rs);

    const double invHW = 1.0 / (double)HW;
    const double invS2 = 1.0 / (double)S2;

    dim3 blk(256);
    dim3 gw2(8, 32, 2);    // conv2: single conv (2 oc-halves)
    dim3 gw8(8, 32, 8);    // conv2: 4 gates x 2 oc-halves
    dim3 gr2(9, 33, 1);    // convr2: 576x528 covers 518x518
    const int NB4 = (CHW/4 + 255) / 256;

    zero_stats<<<1, 256>>>();

    // e1: x (4ch) -> t1, stats stage 0
    conv2<4, 0><<<gw2, blk>>>(x, nullptr, w_e1, w_e1, w_e1, w_e1,
                              t1, 0, sum + 0, sq + 0);
    finalize_stats<<<1, 32>>>(0, 32, invHW);

    // t1n = relu(bn(t1))
    normalize<1><<<NB4, 256>>>(t1, t1n, 0);

    // e2: conv(t1n) -> t2, stats stage 1
    conv2<32, 0><<<gw2, blk>>>(t1n, nullptr, w_e2, w_e2, w_e2, w_e2,
                               t2, 0, sum + 32, sq + 32);
    finalize_stats<<<1, 32>>>(1, 32, invHW);

    // t2n = bn(t2)
    normalize<0><<<NB4, 256>>>(t2, t2n, 1);

    // gates: concat(prev_h, t2n) via split pointers, stats stages 2..5
    conv2<64, 1><<<gw8, blk>>>(t2n, prev_h, w_f, w_i, w_c, w_o,
                               gates, (long)CHW, sum + 64, sq + 64);
    finalize_stats<<<4, 32>>>(2, 32, invHW);

    // LSTM pointwise -> next_c, next_h written directly into d_out
    lstm_elem<<<NB4, 256>>>(prev_c, out);

    // r1: conv(next_h raw) -> r1, stats stage 6
    conv2<32, 0><<<gw2, blk>>>(out + CHW, nullptr, w_r1, w_r1, w_r1, w_r1,
                               r1, 0, sum + 192, sq + 192);
    finalize_stats<<<1, 32>>>(6, 32, invHW);

    // normalize r1 -> reuse t1n buffer as relu(bn(r1))
    normalize<1><<<NB4, 256>>>(r1, t1n, 6);

    // r2: conv(relu(bn(r1))) -> r2 (3ch, 518x518, pad 4), stats stage 7
    convr2<<<gr2, blk>>>(t1n, w_r2, r2, sum + 224, sq + 224);
    finalize_stats<<<1, 32>>>(7, 3, invS2);

    // gather + tiny matmul (K=1 scalar) -> res
    gather_k<<<1, 256>>>(holes, w_oil, b_oil, w_wat, b_wat, w_gas, b_gas, out);
}